// round 10
// baseline (speedup 1.0000x reference)
#include <cuda_runtime.h>
#include <cstdint>

// HMM forward filter — 2 warps per batch, 4 batches per 256-thread CTA, grid=64.
// Each SMSP hosts 2 warps from DIFFERENT batches: independent recurrences
// interleave and fill each other's barrier/LDS/chain bubbles.
// Warp q of a batch owns states i in [32q,32q+32); lane p carries scalar v_i.
//   chain:  t_i = v_i*lik ; STS ; bar(batch) ; 16x LDS.128 ; 32x fma2 ;
//           tree+horiz ; v_i = out_i * f_scale (pow2, lagged)
//   shadow: half-sum shfl butterfly -> smem ; step-(k-1) outputs with exact r.
// T row-stochastic => sum(t@T)=sum(t): one sum normalizes est and pred.

#define Bn 256
#define Hn 2048
#define Sn 64
#define UD 8
#define BATCHES_PER_CTA 4

using u64 = unsigned long long;

__device__ __forceinline__ u64 fma2(u64 a, u64 b, u64 c) {
    u64 d; asm("fma.rn.f32x2 %0, %1, %2, %3;" : "=l"(d) : "l"(a), "l"(b), "l"(c)); return d;
}
__device__ __forceinline__ u64 add2(u64 a, u64 b) {
    u64 d; asm("add.rn.f32x2 %0, %1, %2;" : "=l"(d) : "l"(a), "l"(b)); return d;
}
__device__ __forceinline__ u64 pack2(float lo, float hi) {
    u64 d; asm("mov.b64 %0, {%1, %2};" : "=l"(d) : "f"(lo), "f"(hi)); return d;
}
__device__ __forceinline__ void unpack2(u64 a, float& x, float& y) {
    asm("mov.b64 {%0, %1}, %2;" : "=f"(x), "=f"(y) : "l"(a));
}
__device__ __forceinline__ float fast_rcp(float s) {
    float r; asm("rcp.approx.f32 %0, %1;" : "=f"(r) : "f"(s)); return r;
}
// Named barrier with IMMEDIATE id (templated) — one per local batch.
template <int ID>
__device__ __forceinline__ void bar_imm() {
    asm volatile("bar.sync %0, 64;" :: "n"(ID) : "memory");
}
__device__ __forceinline__ void bar_batch(int lb) {
    switch (lb) {
        case 0: bar_imm<1>(); break;
        case 1: bar_imm<2>(); break;
        case 2: bar_imm<3>(); break;
        default: bar_imm<4>(); break;
    }
}

__global__ void __launch_bounds__(64 * BATCHES_PER_CTA, 1) hmm_forward_kernel(
    const float* __restrict__ lik,    // [B, H, S]
    const float* __restrict__ init_s, // [S]
    const float* __restrict__ Tm,     // [S, S] row-major
    float* __restrict__ est_out,      // [B, H, S]
    float* __restrict__ pred_out)     // [B, H, S]
{
    __shared__ alignas(16) float tbuf[BATCHES_PER_CTA][2][Sn];  // [batch][parity][state]
    __shared__ float ssum[BATCHES_PER_CTA][2][2];               // [batch][parity][half]

    const int tid = threadIdx.x;
    const int lb  = tid >> 6;          // local batch 0..3
    const int bt  = tid & 63;
    const int q   = bt >> 5;           // output half
    const int p   = bt & 31;
    const int i   = 32 * q + p;        // owned state
    const int b   = blockIdx.x * BATCHES_PER_CTA + lb;

    // T column i as input pairs: TTp[m] = {T[2m][i], T[2m+1][i]}
    u64 TTp[32];
#pragma unroll
    for (int m = 0; m < 32; m++)
        TTp[m] = pack2(Tm[(2 * m) * Sn + i], Tm[(2 * m + 1) * Sn + i]);

    const float* likp = lik + (size_t)b * Hn * Sn + i;
    float* eo = est_out  + (size_t)b * Hn * Sn + i;
    float* po = pred_out + (size_t)b * Hn * Sn + i;

    // ---- v = pred0 = init @ T (stage init in parity-1 buffer) ----
    tbuf[lb][1][i] = init_s[i];
    bar_batch(lb);
    float v;
    {
        const ulonglong2* tv = reinterpret_cast<const ulonglong2*>(tbuf[lb][1]);
        u64 a0 = 0, a1 = 0;
#pragma unroll
        for (int t = 0; t < 16; t++) {
            ulonglong2 w = tv[t];
            a0 = fma2(w.x, TTp[2 * t + 0], a0);
            a1 = fma2(w.y, TTp[2 * t + 1], a1);
        }
        u64 s2 = add2(a0, a1);
        float sx, sy; unpack2(s2, sx, sy);
        v = sx + sy;
    }

    // ---- lik FIFO ----
    float fifo[UD];
#pragma unroll
    for (int j = 0; j < UD; j++)
        fifo[j] = likp[(size_t)j * Sn];

    float f_scale = 1.0f;      // pred0 sums to exactly 1
    float t_prev = 0.f, out_prev = 0.f, s_my = 0.f;

    for (int kk = 0; kk < Hn; kk += UD) {
#pragma unroll
        for (int j = 0; j < UD; j++) {
            const int k = kk + j;
            const float lk = fifo[j];
            int kn = k + UD; if (kn > Hn - 1) kn = Hn - 1;
            fifo[j] = likp[(size_t)kn * Sn];

            // ---- chain head: t_i = v_i * lik, publish ----
            const float t = v * lk;
            tbuf[lb][k & 1][i] = t;
            bar_batch(lb);

            // ---- shadow: finish step k-1 (exact r from global sum) ----
            if (k > 0) {
                float s_tot = s_my + ssum[lb][(k - 1) & 1][1 - q];
                s_tot = fmaxf(s_tot, 1e-35f);
                const float r = fast_rcp(s_tot);
                eo[(size_t)(k - 1) * Sn] = t_prev * r;
                po[(size_t)(k - 1) * Sn] = out_prev * r;
                const unsigned eb = (__float_as_uint(s_tot) >> 23) & 0xFFu;
                f_scale = __uint_as_float((254u - eb) << 23);  // exact 2^(127-e)
            }

            // ---- chain: out_i = sum_j t_j T[j][i] ----
            u64 a0 = 0, a1 = 0, a2 = 0, a3 = 0, a4 = 0, a5 = 0, a6 = 0, a7 = 0;
            const ulonglong2* tv = reinterpret_cast<const ulonglong2*>(tbuf[lb][k & 1]);
#pragma unroll
            for (int t4 = 0; t4 < 16; t4 += 4) {
                ulonglong2 w0 = tv[t4 + 0];
                ulonglong2 w1 = tv[t4 + 1];
                ulonglong2 w2 = tv[t4 + 2];
                ulonglong2 w3 = tv[t4 + 3];
                a0 = fma2(w0.x, TTp[2 * t4 + 0], a0);
                a1 = fma2(w0.y, TTp[2 * t4 + 1], a1);
                a2 = fma2(w1.x, TTp[2 * t4 + 2], a2);
                a3 = fma2(w1.y, TTp[2 * t4 + 3], a3);
                a4 = fma2(w2.x, TTp[2 * t4 + 4], a4);
                a5 = fma2(w2.y, TTp[2 * t4 + 5], a5);
                a6 = fma2(w3.x, TTp[2 * t4 + 6], a6);
                a7 = fma2(w3.y, TTp[2 * t4 + 7], a7);
            }
            const u64 s2 = add2(add2(add2(a0, a1), add2(a2, a3)),
                                add2(add2(a4, a5), add2(a6, a7)));
            float sx, sy; unpack2(s2, sx, sy);
            const float out = sx + sy;

            // chain tail: pow2 rescale (factor from shadow, one step lagged)
            v = out * f_scale;

            // ---- shadow: my half-sum for step k ----
            float sm = t;
#pragma unroll
            for (int o = 16; o; o >>= 1) sm += __shfl_xor_sync(0xFFFFFFFFu, sm, o);
            if (p == 0) ssum[lb][k & 1][q] = sm;
            s_my = sm;
            t_prev = t;
            out_prev = out;
        }
    }

    // ---- flush last step's outputs ----
    bar_batch(lb);
    {
        float s_tot = s_my + ssum[lb][(Hn - 1) & 1][1 - q];
        s_tot = fmaxf(s_tot, 1e-35f);
        const float r = fast_rcp(s_tot);
        eo[(size_t)(Hn - 1) * Sn] = t_prev * r;
        po[(size_t)(Hn - 1) * Sn] = out_prev * r;
    }
}

extern "C" void kernel_launch(void* const* d_in, const int* in_sizes, int n_in,
                              void* d_out, int out_size) {
    const float* lik    = (const float*)d_in[0];   // [256, 2048, 64]
    const float* init_s = (const float*)d_in[1];   // [64]
    const float* Tm     = (const float*)d_in[2];   // [64, 64]
    float* eo = (float*)d_out;                      // est_traj first
    float* po = eo + (size_t)Bn * Hn * Sn;          // pred_traj second

    hmm_forward_kernel<<<Bn / BATCHES_PER_CTA, 64 * BATCHES_PER_CTA>>>(lik, init_s, Tm, eo, po);
}

// round 11
// speedup vs baseline: 1.5237x; 1.5237x over previous
#include <cuda_runtime.h>
#include <cstdint>

// HMM forward filter — 2 warps per batch, 2 batches per 128-thread CTA, grid=128
// (R7 shape: 1 warp per SMSP on 128 SMs). NO shuffle reduction: the matvec's
// 16 broadcast LDS.128 give every lane all 64 t-values, so each lane sums them
// locally with 31 add2 (registers already loaded). Same-step normalization,
// no cross-warp sum exchange, no output lag. Per step:
//   chain:  t_i = v_i*lik ; STS ; bar(batch) ; 16x LDS.128 ; 32x fma2 ->out_i ;
//           v_i = out_i * 2^(127-exp(s))   (exact pow2, s ready before out)
//   overlap: s = local add2 tree of the same registers ; r = rcp(s) ;
//            est=t*r, pred=out*r -> STG
// T row-stochastic => sum(t@T)=sum(t): one s normalizes est and pred.

#define Bn 256
#define Hn 2048
#define Sn 64
#define UD 8
#define BATCHES_PER_CTA 2

using u64 = unsigned long long;

__device__ __forceinline__ u64 fma2(u64 a, u64 b, u64 c) {
    u64 d; asm("fma.rn.f32x2 %0, %1, %2, %3;" : "=l"(d) : "l"(a), "l"(b), "l"(c)); return d;
}
__device__ __forceinline__ u64 add2(u64 a, u64 b) {
    u64 d; asm("add.rn.f32x2 %0, %1, %2;" : "=l"(d) : "l"(a), "l"(b)); return d;
}
__device__ __forceinline__ u64 pack2(float lo, float hi) {
    u64 d; asm("mov.b64 %0, {%1, %2};" : "=l"(d) : "f"(lo), "f"(hi)); return d;
}
__device__ __forceinline__ void unpack2(u64 a, float& x, float& y) {
    asm("mov.b64 {%0, %1}, %2;" : "=f"(x), "=f"(y) : "l"(a));
}
__device__ __forceinline__ float fast_rcp(float s) {
    float r; asm("rcp.approx.f32 %0, %1;" : "=f"(r) : "f"(s)); return r;
}
template <int ID>
__device__ __forceinline__ void bar_imm() {
    asm volatile("bar.sync %0, 64;" :: "n"(ID) : "memory");
}
__device__ __forceinline__ void bar_batch(int lb) {
    if (lb == 0) bar_imm<1>(); else bar_imm<2>();
}

__global__ void __launch_bounds__(64 * BATCHES_PER_CTA, 1) hmm_forward_kernel(
    const float* __restrict__ lik,    // [B, H, S]
    const float* __restrict__ init_s, // [S]
    const float* __restrict__ Tm,     // [S, S] row-major
    float* __restrict__ est_out,      // [B, H, S]
    float* __restrict__ pred_out)     // [B, H, S]
{
    __shared__ alignas(16) float tbuf[BATCHES_PER_CTA][2][Sn];  // [batch][parity][state]

    const int tid = threadIdx.x;
    const int lb  = tid >> 6;          // local batch 0/1
    const int bt  = tid & 63;
    const int q   = bt >> 5;           // output half
    const int p   = bt & 31;
    const int i   = 32 * q + p;        // owned state
    const int b   = blockIdx.x * BATCHES_PER_CTA + lb;

    // T column i as input pairs: TTp[m] = {T[2m][i], T[2m+1][i]}
    u64 TTp[32];
#pragma unroll
    for (int m = 0; m < 32; m++)
        TTp[m] = pack2(Tm[(2 * m) * Sn + i], Tm[(2 * m + 1) * Sn + i]);

    const float* likp = lik + (size_t)b * Hn * Sn + i;
    float* eo = est_out  + (size_t)b * Hn * Sn + i;
    float* po = pred_out + (size_t)b * Hn * Sn + i;

    // ---- v = pred0 = init @ T (stage init in parity-1 buffer) ----
    tbuf[lb][1][i] = init_s[i];
    bar_batch(lb);
    float v;
    {
        const ulonglong2* tv = reinterpret_cast<const ulonglong2*>(tbuf[lb][1]);
        u64 a0 = 0, a1 = 0;
#pragma unroll
        for (int t = 0; t < 16; t++) {
            ulonglong2 w = tv[t];
            a0 = fma2(w.x, TTp[2 * t + 0], a0);
            a1 = fma2(w.y, TTp[2 * t + 1], a1);
        }
        u64 s2 = add2(a0, a1);
        float sx, sy; unpack2(s2, sx, sy);
        v = sx + sy;
    }

    // ---- lik FIFO ----
    float fifo[UD];
#pragma unroll
    for (int j = 0; j < UD; j++)
        fifo[j] = likp[(size_t)j * Sn];

    for (int kk = 0; kk < Hn; kk += UD) {
#pragma unroll
        for (int j = 0; j < UD; j++) {
            const int k = kk + j;
            const float lk = fifo[j];
            int kn = k + UD; if (kn > Hn - 1) kn = Hn - 1;
            fifo[j] = likp[(size_t)kn * Sn];

            // ---- chain head: t_i = v_i * lik, publish ----
            const float t = v * lk;
            tbuf[lb][k & 1][i] = t;
            bar_batch(lb);

            // ---- matvec + local full-sum from the SAME loaded registers ----
            u64 a0, a1, a2, a3, a4, a5, a6, a7;       // matvec accums
            u64 s0, s1, s2a, s3a, s4a, s5a, s6a, s7a; // sum accums
            const ulonglong2* tv = reinterpret_cast<const ulonglong2*>(tbuf[lb][k & 1]);
#pragma unroll
            for (int t4 = 0; t4 < 16; t4 += 4) {
                ulonglong2 w0 = tv[t4 + 0];
                ulonglong2 w1 = tv[t4 + 1];
                ulonglong2 w2 = tv[t4 + 2];
                ulonglong2 w3 = tv[t4 + 3];
                if (t4 == 0) {
                    a0 = fma2(w0.x, TTp[0], 0); a1 = fma2(w0.y, TTp[1], 0);
                    a2 = fma2(w1.x, TTp[2], 0); a3 = fma2(w1.y, TTp[3], 0);
                    a4 = fma2(w2.x, TTp[4], 0); a5 = fma2(w2.y, TTp[5], 0);
                    a6 = fma2(w3.x, TTp[6], 0); a7 = fma2(w3.y, TTp[7], 0);
                    s0 = w0.x; s1 = w0.y; s2a = w1.x; s3a = w1.y;
                    s4a = w2.x; s5a = w2.y; s6a = w3.x; s7a = w3.y;
                } else {
                    a0 = fma2(w0.x, TTp[2 * t4 + 0], a0);
                    a1 = fma2(w0.y, TTp[2 * t4 + 1], a1);
                    a2 = fma2(w1.x, TTp[2 * t4 + 2], a2);
                    a3 = fma2(w1.y, TTp[2 * t4 + 3], a3);
                    a4 = fma2(w2.x, TTp[2 * t4 + 4], a4);
                    a5 = fma2(w2.y, TTp[2 * t4 + 5], a5);
                    a6 = fma2(w3.x, TTp[2 * t4 + 6], a6);
                    a7 = fma2(w3.y, TTp[2 * t4 + 7], a7);
                    s0 = add2(s0, w0.x); s1 = add2(s1, w0.y);
                    s2a = add2(s2a, w1.x); s3a = add2(s3a, w1.y);
                    s4a = add2(s4a, w2.x); s5a = add2(s5a, w2.y);
                    s6a = add2(s6a, w3.x); s7a = add2(s7a, w3.y);
                }
            }
            // sum tree (ready before matvec tail — shares the same LDS data)
            const u64 sp = add2(add2(add2(s0, s1), add2(s2a, s3a)),
                                add2(add2(s4a, s5a), add2(s6a, s7a)));
            float ssx, ssy; unpack2(sp, ssx, ssy);
            float s = fmaxf(ssx + ssy, 1e-35f);
            const float r = fast_rcp(s);
            const unsigned eb = (__float_as_uint(s) >> 23) & 0xFFu;
            const float f = __uint_as_float((254u - eb) << 23);   // exact 2^(127-e)

            // matvec tail
            const u64 o2 = add2(add2(add2(a0, a1), add2(a2, a3)),
                                add2(add2(a4, a5), add2(a6, a7)));
            float ox, oy; unpack2(o2, ox, oy);
            const float out = ox + oy;

            // chain tail: exact pow2 rescale (f ready before out)
            v = out * f;

            // overlap: normalized outputs
            eo[(size_t)k * Sn] = t * r;
            po[(size_t)k * Sn] = out * r;
        }
    }
}

extern "C" void kernel_launch(void* const* d_in, const int* in_sizes, int n_in,
                              void* d_out, int out_size) {
    const float* lik    = (const float*)d_in[0];   // [256, 2048, 64]
    const float* init_s = (const float*)d_in[1];   // [64]
    const float* Tm     = (const float*)d_in[2];   // [64, 64]
    float* eo = (float*)d_out;                      // est_traj first
    float* po = eo + (size_t)Bn * Hn * Sn;          // pred_traj second

    hmm_forward_kernel<<<Bn / BATCHES_PER_CTA, 64 * BATCHES_PER_CTA>>>(lik, init_s, Tm, eo, po);
}